// round 6
// baseline (speedup 1.0000x reference)
#include <cuda_runtime.h>
#include <cstdint>

// ---------------- problem constants ----------------
#define BATCH   8
#define SEQ     16384
#define CH      128
#define WIN     32
#define STRD    16
#define NB      1023
#define MROWS   (BATCH*NB)           // 8184
#define K1      4096
#define N1      256
#define K2      256
#define N2      128

// ---------------- scratch (__device__ globals; no allocation) ----------------
__device__ float g_b1p[N1];
__device__ float g_partial[32 * N1];
__device__ float g_h[(size_t)MROWS * N1];     // 8.4 MB intermediate
__device__ float g_W1t[(size_t)N1 * K1];      // 4 MB transposed + tf32-rounded W1

// ---------------- helpers ----------------
__device__ __forceinline__ uint32_t cvt_tf32(float x) {
    uint32_t u; asm("cvt.rna.tf32.f32 %0, %1;" : "=r"(u) : "f"(x)); return u;
}
__device__ __forceinline__ float rna_tf32_f(float x) {
    uint32_t u = cvt_tf32(x); return __uint_as_float(u);
}
__device__ __forceinline__ void mma_tf32(float c[4], const uint32_t a[4], const uint32_t b[2]) {
    asm volatile(
        "mma.sync.aligned.m16n8k8.row.col.f32.tf32.tf32.f32 "
        "{%0,%1,%2,%3}, {%4,%5,%6,%7}, {%8,%9}, {%0,%1,%2,%3};"
        : "+f"(c[0]), "+f"(c[1]), "+f"(c[2]), "+f"(c[3])
        : "r"(a[0]), "r"(a[1]), "r"(a[2]), "r"(a[3]), "r"(b[0]), "r"(b[1]));
}
__device__ __forceinline__ void cp_async16(uint32_t dst, const void* src) {
    asm volatile("cp.async.cg.shared.global [%0], [%1], 16;" :: "r"(dst), "l"(src));
}
__device__ __forceinline__ void cp_commit() {
    asm volatile("cp.async.commit_group;");
}
__device__ __forceinline__ float gelu_exact(float v) {
    return 0.5f * v * (1.0f + erff(v * 0.70710678118654752f));
}

// ---------------- pre-kernels ----------------
__global__ void pos_w1_partial(const float* __restrict__ pos, const float* __restrict__ W1) {
    int kc = blockIdx.x;
    int n  = threadIdx.x;
    int k0 = kc * 128;
    float s = 0.f;
    #pragma unroll 4
    for (int k = 0; k < 128; k++)
        s += pos[k0 + k] * W1[(size_t)(k0 + k) * N1 + n];
    g_partial[kc * N1 + n] = s;
}
__global__ void pos_w1_reduce(const float* __restrict__ b1) {
    int n = threadIdx.x;
    float s = b1[n];
    #pragma unroll
    for (int i = 0; i < 32; i++) s += g_partial[i * N1 + n];
    g_b1p[n] = s;
}
// W1 (K1,N1) -> g_W1t (N1,K1), rna-rounded to tf32 bit pattern
__global__ void transpose_w1(const float* __restrict__ W1) {
    __shared__ float tile[32][33];
    int k0 = blockIdx.x * 32, n0 = blockIdx.y * 32;
    int tx = threadIdx.x, ty = threadIdx.y;   // 32 x 8
    #pragma unroll
    for (int i = 0; i < 32; i += 8)
        tile[ty + i][tx] = W1[(size_t)(k0 + ty + i) * N1 + n0 + tx];
    __syncthreads();
    #pragma unroll
    for (int i = 0; i < 32; i += 8)
        g_W1t[(size_t)(n0 + ty + i) * K1 + k0 + tx] = rna_tf32_f(tile[tx][ty + i]);
}

// ================= kernel 1: h = gelu(gather(x) @ W1 + b1') =================
// BM=224, BN=64, BK=32. Grid 37 x 4 = 148 CTAs = exactly one full wave.
// A smem: 224 rows x stride 36 ; B smem ([n][k]): 64 rows x stride 36.
#define K1_BM     224
#define K1_BN     64
#define K1_STR    36
#define K1_AELE   (K1_BM * K1_STR)    // 8064
#define K1_BELE   (K1_BN * K1_STR)    // 2304
#define K1_STAGE  (K1_AELE + K1_BELE) // 10368 floats
#define K1_STAGES 3
#define K1_SMEM   (K1_STAGES * K1_STAGE * 4)   // 124416 B
#define K1_NCHUNK (K1 / 32)                    // 128
#define K1_MT     37                           // ceil(8184/224)

__global__ __launch_bounds__(256, 1)
void k1_gemm_gelu(const float* __restrict__ x) {
    extern __shared__ float smem[];

    const int tid   = threadIdx.x;
    const int lane  = tid & 31;
    const int warp  = tid >> 5;
    const int warpM = warp >> 2;      // 0..1  (112 rows each)
    const int warpN = warp & 3;       // 0..3  (16 cols each)
    const int qr    = lane >> 2;      // 0..7
    const int qc    = lane & 3;       // 0..3
    const int mtile = blockIdx.x;     // 0..36
    const int ntile = blockIdx.y;     // 0..3

    // ---- A loader: 7 passes of 32 rows x 8 16B-chunks ----
    const int lrow = tid >> 3;        // 0..31
    const int lcol = tid & 7;         // 0..7
    int tokbase[7];
    #pragma unroll
    for (int p = 0; p < 7; p++) {
        int m  = mtile * K1_BM + p * 32 + lrow;
        int mc = (m < MROWS) ? m : (MROWS - 1);   // clamp; stores predicated
        int b  = mc / NB;
        tokbase[p] = b * SEQ + (mc - b * NB) * STRD;
    }
    // ---- B loader: 64 rows x 8 chunks, 2 chunks/thread ----
    const int brow   = tid >> 2;      // 0..63
    const int bch2   = (tid & 3) * 2; // 0,2,4,6
    const float* brow_base = g_W1t + (size_t)(ntile * K1_BN + brow) * K1;

    auto load_chunk = [&](int kc) {
        float* As = smem + (kc % K1_STAGES) * K1_STAGE;
        float* Bs = As + K1_AELE;
        const int t   = kc >> 2;              // token in window
        const int ch0 = (kc & 3) * 32;        // channel base
        #pragma unroll
        for (int p = 0; p < 7; p++) {
            const float* src = x + (size_t)(tokbase[p] + t) * CH + ch0 + lcol * 4;
            uint32_t dst = (uint32_t)__cvta_generic_to_shared(
                As + (p * 32 + lrow) * K1_STR + lcol * 4);
            cp_async16(dst, src);
        }
        #pragma unroll
        for (int i = 0; i < 2; i++) {
            int ck = bch2 + i;
            const float* src = brow_base + kc * 32 + ck * 4;
            uint32_t dst = (uint32_t)__cvta_generic_to_shared(
                Bs + brow * K1_STR + ck * 4);
            cp_async16(dst, src);
        }
        cp_commit();
    };

    float acc[7][2][4];
    #pragma unroll
    for (int a = 0; a < 7; a++)
        #pragma unroll
        for (int b = 0; b < 2; b++)
            #pragma unroll
            for (int c = 0; c < 4; c++) acc[a][b][c] = 0.f;

    load_chunk(0);
    load_chunk(1);

    for (int kc = 0; kc < K1_NCHUNK; kc++) {
        asm volatile("cp.async.wait_group %0;" :: "n"(K1_STAGES - 2));
        __syncthreads();
        if (kc + 2 < K1_NCHUNK) load_chunk(kc + 2);

        const float* As = smem + (kc % K1_STAGES) * K1_STAGE;
        const float* Bs = As + K1_AELE;
        #pragma unroll
        for (int ks = 0; ks < 4; ks++) {
            uint32_t af[7][4];
            #pragma unroll
            for (int mi = 0; mi < 7; mi++) {
                int r0 = warpM * 112 + mi * 16 + qr;
                af[mi][0] = cvt_tf32(As[ r0      * K1_STR + ks * 8 + qc    ]);
                af[mi][1] = cvt_tf32(As[(r0 + 8) * K1_STR + ks * 8 + qc    ]);
                af[mi][2] = cvt_tf32(As[ r0      * K1_STR + ks * 8 + qc + 4]);
                af[mi][3] = cvt_tf32(As[(r0 + 8) * K1_STR + ks * 8 + qc + 4]);
            }
            #pragma unroll
            for (int ni = 0; ni < 2; ni++) {
                int n = warpN * 16 + ni * 8 + qr;
                uint32_t bf[2];
                bf[0] = __float_as_uint(Bs[n * K1_STR + ks * 8 + qc    ]);  // pre-rounded
                bf[1] = __float_as_uint(Bs[n * K1_STR + ks * 8 + qc + 4]);
                #pragma unroll
                for (int mi = 0; mi < 7; mi++)
                    mma_tf32(acc[mi][ni], af[mi], bf);
            }
        }
    }

    // ---- epilogue: bias + exact GELU -> g_h ----
    #pragma unroll
    for (int ni = 0; ni < 2; ni++) {
        int col = ntile * K1_BN + warpN * 16 + ni * 8 + qc * 2;
        float bs0 = g_b1p[col], bs1 = g_b1p[col + 1];
        #pragma unroll
        for (int mi = 0; mi < 7; mi++) {
            #pragma unroll
            for (int half = 0; half < 2; half++) {
                int m = mtile * K1_BM + warpM * 112 + mi * 16 + qr + half * 8;
                if (m < MROWS) {
                    float v0 = gelu_exact(acc[mi][ni][half * 2 + 0] + bs0);
                    float v1 = gelu_exact(acc[mi][ni][half * 2 + 1] + bs1);
                    *(float2*)(g_h + (size_t)m * N1 + col) = make_float2(v0, v1);
                }
            }
        }
    }
}

// ================= kernel 2: out = h @ W2 + b2 =================
// BM=64, BN=128, BK=32. Grid 128 CTAs.
#define K2_BM    64
#define K2_BN    128
#define K2_ASTR  36
#define K2_BSTR  136
#define K2_AELE  (K2_BM * K2_ASTR)    // 2304
#define K2_BELE  (32 * K2_BSTR)       // 4352
#define K2_STAGE (K2_AELE + K2_BELE)  // 6656 floats
#define K2_STAGES 3
#define K2_SMEM  (K2_STAGES * K2_STAGE * 4)   // 79872 B
#define K2_NCHUNK (K2 / 32)                   // 8

__global__ __launch_bounds__(256, 1)
void k2_gemm(const float* __restrict__ W2, const float* __restrict__ b2,
             float* __restrict__ out) {
    extern __shared__ float smem[];

    const int tid   = threadIdx.x;
    const int lane  = tid & 31;
    const int warp  = tid >> 5;
    const int warpM = warp >> 2;      // 0..1 (32 rows)
    const int warpN = warp & 3;       // 0..3 (32 cols)
    const int qr    = lane >> 2;
    const int qc    = lane & 3;
    const int mtile = blockIdx.x;     // 0..127

    // A loader: 64 rows x 8 chunks, 2 chunks/thread (1 row each)
    const int arow = tid >> 2;        // 0..63
    const int ach2 = (tid & 3) * 2;
    int m0 = mtile * K2_BM + arow;
    const int mrow = (m0 < MROWS) ? m0 : (MROWS - 1);
    // B loader: 32 k-rows x 32 chunks (4 rows/thread as before)
    const int bkrow = tid >> 5;       // 0..7
    const int bcol4 = tid & 31;       // 0..31

    auto load_chunk = [&](int kc) {
        float* As = smem + (kc % K2_STAGES) * K2_STAGE;
        float* Bs = As + K2_AELE;
        #pragma unroll
        for (int i = 0; i < 2; i++) {
            int ck = ach2 + i;
            const float* src = g_h + (size_t)mrow * K2 + kc * 32 + ck * 4;
            uint32_t dst = (uint32_t)__cvta_generic_to_shared(
                As + arow * K2_ASTR + ck * 4);
            cp_async16(dst, src);
        }
        #pragma unroll
        for (int i = 0; i < 4; i++) {
            int kr = bkrow + i * 8;
            const float* src = W2 + (size_t)(kc * 32 + kr) * N2 + bcol4 * 4;
            uint32_t dst = (uint32_t)__cvta_generic_to_shared(
                Bs + kr * K2_BSTR + bcol4 * 4);
            cp_async16(dst, src);
        }
        cp_commit();
    };

    float acc[2][4][4];
    #pragma unroll
    for (int a = 0; a < 2; a++)
        #pragma unroll
        for (int b = 0; b < 4; b++)
            #pragma unroll
            for (int c = 0; c < 4; c++) acc[a][b][c] = 0.f;

    load_chunk(0);
    load_chunk(1);

    for (int kc = 0; kc < K2_NCHUNK; kc++) {
        asm volatile("cp.async.wait_group %0;" :: "n"(K2_STAGES - 2));
        __syncthreads();
        if (kc + 2 < K2_NCHUNK) load_chunk(kc + 2);

        const float* As = smem + (kc % K2_STAGES) * K2_STAGE;
        const float* Bs = As + K2_AELE;
        #pragma unroll
        for (int ks = 0; ks < 4; ks++) {
            uint32_t af[2][4];
            #pragma unroll
            for (int mi = 0; mi < 2; mi++) {
                int r0 = warpM * 32 + mi * 16 + qr;
                af[mi][0] = cvt_tf32(As[ r0      * K2_ASTR + ks * 8 + qc    ]);
                af[mi][1] = cvt_tf32(As[(r0 + 8) * K2_ASTR + ks * 8 + qc    ]);
                af[mi][2] = cvt_tf32(As[ r0      * K2_ASTR + ks * 8 + qc + 4]);
                af[mi][3] = cvt_tf32(As[(r0 + 8) * K2_ASTR + ks * 8 + qc + 4]);
            }
            #pragma unroll
            for (int ni = 0; ni < 4; ni++) {
                int c0 = warpN * 32 + ni * 8 + qr;
                uint32_t bf[2];
                bf[0] = cvt_tf32(Bs[(ks * 8 + qc    ) * K2_BSTR + c0]);
                bf[1] = cvt_tf32(Bs[(ks * 8 + qc + 4) * K2_BSTR + c0]);
                #pragma unroll
                for (int mi = 0; mi < 2; mi++)
                    mma_tf32(acc[mi][ni], af[mi], bf);
            }
        }
    }

    #pragma unroll
    for (int ni = 0; ni < 4; ni++) {
        int col = warpN * 32 + ni * 8 + qc * 2;
        float bs0 = b2[col], bs1 = b2[col + 1];
        #pragma unroll
        for (int mi = 0; mi < 2; mi++) {
            #pragma unroll
            for (int half = 0; half < 2; half++) {
                int m = mtile * K2_BM + warpM * 32 + mi * 16 + qr + half * 8;
                if (m < MROWS) {
                    float v0 = acc[mi][ni][half * 2 + 0] + bs0;
                    float v1 = acc[mi][ni][half * 2 + 1] + bs1;
                    *(float2*)(out + (size_t)m * N2 + col) = make_float2(v0, v1);
                }
            }
        }
    }
}

// ---------------- launch ----------------
extern "C" void kernel_launch(void* const* d_in, const int* in_sizes, int n_in,
                              void* d_out, int out_size) {
    const float* x   = (const float*)d_in[0];
    const float* pos = (const float*)d_in[1];
    const float* W1  = (const float*)d_in[2];
    const float* b1  = (const float*)d_in[3];
    const float* W2  = (const float*)d_in[4];
    const float* b2  = (const float*)d_in[5];
    float* out = (float*)d_out;

    cudaFuncSetAttribute(k1_gemm_gelu, cudaFuncAttributeMaxDynamicSharedMemorySize, K1_SMEM);
    cudaFuncSetAttribute(k2_gemm,      cudaFuncAttributeMaxDynamicSharedMemorySize, K2_SMEM);

    // W1 transpose (+ tf32 rna pre-round) and pos-folded bias
    dim3 tb(32, 8);
    transpose_w1<<<dim3(K1 / 32, N1 / 32), tb>>>(W1);
    pos_w1_partial<<<32, 256>>>(pos, W1);
    pos_w1_reduce<<<1, 256>>>(b1);

    dim3 g1(K1_MT, 4);                 // 37 x 4 = 148 CTAs
    k1_gemm_gelu<<<g1, 256, K1_SMEM>>>(x);

    k2_gemm<<<128, 256, K2_SMEM>>>(W2, b2, out);
}